// round 1
// baseline (speedup 1.0000x reference)
#include <cuda_runtime.h>

#define NB 2
#define NP 524288           // points per batch
#define NG 1024             // oversampled grid per dim
#define NF 512              // frequency grid per dim
#define ROWC 1032           // padded row length in complex (8 wrap columns)
#define ROWF4 516           // padded row length in float4 (2 complex each)
#define BETA_F 4.712388980384690f   // 1.5*pi
#define DPI 3.14159265358979323846

// ---------------- static device scratch (no allocations allowed) ----------------
__device__ float2 d_spec[NB * NG * NG];        // FFT working buffer (a -> g), 16.8 MB
__device__ float4 d_gE[NB * NG * ROWF4];       // even-parity padded copy of g
__device__ float4 d_gO[NB * NG * ROWF4];       // shifted-by-one padded copy of g
__device__ float  d_cinv[NF];                  // 1 / phi_hat_1d coefficients
__device__ float2 d_tw[NG];                    // e^{-2 pi i j / 1024}

// ---------------- init: deconvolution coefficients + twiddles ----------------
__global__ void init_kernel() {
    int t = blockIdx.x * blockDim.x + threadIdx.x;
    if (t < NF) {
        double k   = (double)(t - 256);
        double w   = 2.0 * DPI * k / 1024.0;
        double bet = 1.5 * DPI;
        double arg = sqrt(bet * bet - w * w);
        double x   = 4.0 * arg;                 // M * arg, always >= 17.7
        // Abramowitz-Stegun asymptotic I0
        double tt = 3.75 / x;
        double poly = 0.39894228 + tt*(0.01328592 + tt*(0.00225319 + tt*(-0.00157565 +
                      tt*(0.00916281 + tt*(-0.02057706 + tt*(0.02635537 +
                      tt*(-0.01647633 + tt*0.00392377)))))));
        double i0 = exp(x) / sqrt(x) * poly;
        d_cinv[t] = (float)(1024.0 / i0);       // 1 / (I0(..)/n)
    }
    if (t < NG) {
        double th = -2.0 * DPI * (double)t / 1024.0;
        d_tw[t] = make_float2((float)cos(th), (float)sin(th));
    }
}

// ---------------- build ifftshifted, deconvolved, scaled spectrum ----------------
__global__ void spectrum_kernel(const float* __restrict__ fhat) {
    int gid = blockIdx.x * blockDim.x + threadIdx.x;   // [0, NB*NG*NG)
    int m2 = gid & 1023;
    int m1 = (gid >> 10) & 1023;
    int b  = gid >> 20;
    float2 v = make_float2(0.0f, 0.0f);
    bool n1 = (m1 < 256) | (m1 >= 768);
    bool n2 = (m2 < 256) | (m2 >= 768);
    if (n1 & n2) {
        int i1 = (m1 < 256) ? (m1 + 256) : (m1 - 768);
        int i2 = (m2 < 256) ? (m2 + 256) : (m2 - 768);
        const float2* fh = (const float2*)fhat;
        float2 f = fh[(b * 512 + i1) * 512 + i2];
        float s = d_cinv[i1] * d_cinv[i2] * (1.0f / 1048576.0f);
        v = make_float2(f.x * s, f.y * s);
    }
    d_spec[gid] = v;
}

__device__ __forceinline__ float2 cmulf(float2 a, float2 b) {
    return make_float2(a.x * b.x - a.y * b.y, a.x * b.y + a.y * b.x);
}

// ---------------- 1024-pt Stockham FFT over contiguous rows ----------------
// Only the 512 rows with nonzero data are transformed (others stay zero).
__global__ void fft_rows_kernel() {
    __shared__ float2 sA[1024];
    __shared__ float2 sB[1024];
    int bi = blockIdx.x;                  // [0, 1024): 2 batches x 512 nonzero rows
    int b  = bi >> 9;
    int rr = bi & 511;
    int row = (rr < 256) ? rr : rr + 512;
    float2* base = d_spec + (b << 20) + (row << 10);
    int t = threadIdx.x;                  // 512 threads
    sA[t]       = base[t];
    sA[t + 512] = base[t + 512];
    __syncthreads();
    float2* x = sA;
    float2* y = sB;
#pragma unroll
    for (int k = 0; k < 10; k++) {
        int s  = 1 << k;
        int sp = t & ~(s - 1);            // s * p
        float2 a  = x[t];
        float2 c  = x[t + 512];
        float2 wp = d_tw[sp];
        float2 sum = make_float2(a.x + c.x, a.y + c.y);
        float2 dif = make_float2(a.x - c.x, a.y - c.y);
        y[t + sp]     = sum;
        y[t + sp + s] = cmulf(dif, wp);
        __syncthreads();
        float2* tmp = x; x = y; y = tmp;
    }
    base[t]       = x[t];
    base[t + 512] = x[t + 512];
}

// ---------------- 1024-pt Stockham FFT over strided columns ----------------
__global__ void fft_cols_kernel() {
    __shared__ float2 sA[1024];
    __shared__ float2 sB[1024];
    int bi  = blockIdx.x;                 // [0, 2048)
    int b   = bi >> 10;
    int col = bi & 1023;
    float2* base = d_spec + (b << 20) + col;
    int t = threadIdx.x;
    sA[t]       = base[(size_t)t << 10];
    sA[t + 512] = base[(size_t)(t + 512) << 10];
    __syncthreads();
    float2* x = sA;
    float2* y = sB;
#pragma unroll
    for (int k = 0; k < 10; k++) {
        int s  = 1 << k;
        int sp = t & ~(s - 1);
        float2 a  = x[t];
        float2 c  = x[t + 512];
        float2 wp = d_tw[sp];
        float2 sum = make_float2(a.x + c.x, a.y + c.y);
        float2 dif = make_float2(a.x - c.x, a.y - c.y);
        y[t + sp]     = sum;
        y[t + sp + s] = cmulf(dif, wp);
        __syncthreads();
        float2* tmp = x; x = y; y = tmp;
    }
    base[(size_t)t << 10]         = x[t];
    base[(size_t)(t + 512) << 10] = x[t + 512];
}

// ---------------- build dual parity padded gather buffers ----------------
__global__ void pad_kernel() {
    int gid = blockIdx.x * blockDim.x + threadIdx.x;   // [0, NB*NG*ROWC)
    int c = gid % ROWC;
    int rb = gid / ROWC;
    int r = rb & 1023;
    int b = rb >> 10;
    const float2* g = d_spec + (b << 20) + (r << 10);
    float2* gE = (float2*)d_gE;
    float2* gO = (float2*)d_gO;
    gE[gid] = g[c & 1023];
    gO[gid] = g[(c + 1) & 1023];
}

// ---------------- Kaiser-Bessel time-domain window ----------------
__device__ __forceinline__ float kbwin(float s) {
    float u2 = fmaf(-s, s, 16.0f);            // M^2 - s^2, always >= 0 here
    if (u2 <= 0.0f) return 0.0f;
    float rinv = rsqrtf(u2);                  // 1/u
    float u    = u2 * rinv;
    float e    = __expf(BETA_F * u);
    float einv = __fdividef(1.0f, e);
    return (e - einv) * rinv * 0.159154943091895336f;  // sinh(b u)/(pi u)
}

// ---------------- per-point 8x8 gather ----------------
__global__ void __launch_bounds__(256) gather_kernel(const float* __restrict__ xin,
                                                     float* __restrict__ out) {
    int gid = blockIdx.x * blockDim.x + threadIdx.x;   // [0, NB*NP)
    int b = gid >> 19;
    float2 xy = ((const float2*)xin)[gid];

    float xn1 = xy.x * 1024.0f;
    float fl1 = floorf(xn1);
    int   l01 = (int)fl1;
    float fr1 = xn1 - fl1;

    float xn2 = xy.y * 1024.0f;
    float fl2 = floorf(xn2);
    int   l02 = (int)fl2;
    float fr2 = xn2 - fl2;

    float w1[8], w2[8];
#pragma unroll
    for (int t = 0; t < 8; t++) {
        float o = (float)(t - 3);
        w1[t] = kbwin(fr1 - o);
        w2[t] = kbwin(fr2 - o);
    }

    int c0 = (l02 - 3) & 1023;
    const float4* gbase = ((c0 & 1) ? d_gO : d_gE)
                        + (size_t)b * (NG * ROWF4) + (c0 >> 1);

    float accre = 0.0f, accim = 0.0f;
#pragma unroll
    for (int i = 0; i < 8; i++) {
        int r = (l01 + i - 3) & 1023;
        const float4* rp = gbase + r * ROWF4;
        float4 q0 = __ldg(rp + 0);
        float4 q1 = __ldg(rp + 1);
        float4 q2 = __ldg(rp + 2);
        float4 q3 = __ldg(rp + 3);
        float sre = w2[0]*q0.x + w2[1]*q0.z + w2[2]*q1.x + w2[3]*q1.z
                  + w2[4]*q2.x + w2[5]*q2.z + w2[6]*q3.x + w2[7]*q3.z;
        float sim = w2[0]*q0.y + w2[1]*q0.w + w2[2]*q1.y + w2[3]*q1.w
                  + w2[4]*q2.y + w2[5]*q2.w + w2[6]*q3.y + w2[7]*q3.w;
        accre = fmaf(w1[i], sre, accre);
        accim = fmaf(w1[i], sim, accim);
    }
    ((float2*)out)[gid] = make_float2(accre, accim);
}

// ---------------- launch ----------------
extern "C" void kernel_launch(void* const* d_in, const int* in_sizes, int n_in,
                              void* d_out, int out_size) {
    const float* xin = (const float*)d_in[0];   // [B, P, 2]   = 2,097,152 floats
    const float* fh  = (const float*)d_in[1];   // [B,512,512,2] = 1,048,576 floats
    if (n_in >= 2 && in_sizes[0] < in_sizes[1]) {  // robustness: x is the larger input
        const float* t = xin; xin = fh; fh = t;
    }
    init_kernel<<<4, 256>>>();
    spectrum_kernel<<<(NB * NG * NG) / 256, 256>>>(fh);
    fft_rows_kernel<<<NB * 512, 512>>>();
    fft_cols_kernel<<<NB * NG, 512>>>();
    pad_kernel<<<(NB * NG * ROWC) / 256, 256>>>();
    gather_kernel<<<(NB * NP) / 256, 256>>>(xin, (float*)d_out);
}

// round 3
// speedup vs baseline: 1.1041x; 1.1041x over previous
#include <cuda_runtime.h>

#define NB 2
#define NP 524288           // points per batch
#define NG 1024             // oversampled grid per dim
#define NF 512              // frequency grid per dim
#define ROWC 1032           // padded row length in complex (8 wrap columns)
#define ROWF4 516           // padded row length in float4 (2 complex each)
#define BETA_F 4.712388980384690f   // 1.5*pi
#define DPI 3.14159265358979323846

// ---------------- static device scratch (no allocations allowed) ----------------
__device__ float2 d_spec[NB * NG * NG];        // row-FFT result (only 512 rows/batch valid)
__device__ float4 d_gE[NB * NG * ROWF4];       // even-parity padded copy of g
__device__ float4 d_gO[NB * NG * ROWF4];       // shifted-by-one padded copy of g
__device__ float  d_cinv[NF];                  // 1 / I0(M*arg) deconvolution coefficients
__device__ float2 d_tw[NG];                    // e^{-2 pi i j / 1024}

// ---------------- init: deconvolution coefficients + twiddles ----------------
__global__ void init_kernel() {
    int t = blockIdx.x * blockDim.x + threadIdx.x;
    if (t < NF) {
        double k   = (double)(t - 256);
        double w   = 2.0 * DPI * k / 1024.0;
        double bet = 1.5 * DPI;
        double arg = sqrt(bet * bet - w * w);
        double x   = 4.0 * arg;                 // M * arg, always >= 17.7
        // Abramowitz-Stegun asymptotic I0
        double tt = 3.75 / x;
        double poly = 0.39894228 + tt*(0.01328592 + tt*(0.00225319 + tt*(-0.00157565 +
                      tt*(0.00916281 + tt*(-0.02057706 + tt*(0.02635537 +
                      tt*(-0.01647633 + tt*0.00392377)))))));
        double i0 = exp(x) / sqrt(x) * poly;
        d_cinv[t] = (float)(1.0 / i0);          // (1024/i0)^2 * (1/1024^2) == (1/i0)^2
    }
    if (t < NG) {
        double th = -2.0 * DPI * (double)t / 1024.0;
        d_tw[t] = make_float2((float)cos(th), (float)sin(th));
    }
}

__device__ __forceinline__ float2 cmulf(float2 a, float2 b) {
    return make_float2(a.x * b.x - a.y * b.y, a.x * b.y + a.y * b.x);
}

// ---------------- fused: deconvolve + ifftshift + 1024-pt row FFT ----------------
// Only the 512 nonzero spectrum rows are produced; zero rows are never written.
__global__ void fft_rows_fused(const float* __restrict__ fhat) {
    __shared__ float2 sA[1024];
    __shared__ float2 sB[1024];
    int bi = blockIdx.x;                  // [0, 1024): 2 batches x 512 nonzero rows
    int b  = bi >> 9;
    int rr = bi & 511;
    int m1 = (rr < 256) ? rr : rr + 512;        // output spectrum row
    int i1 = (rr < 256) ? rr + 256 : rr - 256;  // source fhat row
    float ci1 = d_cinv[i1];
    const float2* fh = (const float2*)fhat + (size_t)(b * 512 + i1) * 512;
    int t = threadIdx.x;                  // 512 threads
#pragma unroll
    for (int h = 0; h < 2; h++) {
        int m2 = t + h * 512;
        float2 v = make_float2(0.0f, 0.0f);
        if (m2 < 256 || m2 >= 768) {
            int i2 = (m2 < 256) ? m2 + 256 : m2 - 768;
            float2 f = fh[i2];
            float s = ci1 * d_cinv[i2];
            v = make_float2(f.x * s, f.y * s);
        }
        sA[m2] = v;
    }
    __syncthreads();
    float2* x = sA;
    float2* y = sB;
#pragma unroll
    for (int k = 0; k < 10; k++) {
        int s  = 1 << k;
        int sp = t & ~(s - 1);
        float2 a  = x[t];
        float2 c  = x[t + 512];
        float2 wp = d_tw[sp];
        float2 sum = make_float2(a.x + c.x, a.y + c.y);
        float2 dif = make_float2(a.x - c.x, a.y - c.y);
        y[t + sp]     = sum;
        y[t + sp + s] = cmulf(dif, wp);
        __syncthreads();
        float2* tmp = x; x = y; y = tmp;
    }
    float2* base = d_spec + (b << 20) + (m1 << 10);
    base[t]       = x[t];
    base[t + 512] = x[t + 512];
}

// ---------------- fused: 4-column 1024-pt FFT + gE/gO epilogue ----------------
// Stage 0 reads only the 512 nonzero rows from gmem (pair u / u+512 has exactly
// one nonzero member). Output written directly into the padded gather buffers.
__global__ void fft_cols_fused() {
    extern __shared__ float2 sm[];        // [0,4096) = buf A, [4096,8192) = buf B
    float2* x = sm;
    float2* y = sm + 4096;
    int bi = blockIdx.x;                  // [0, 512)
    int b  = bi >> 8;
    int c0 = (bi & 255) << 2;             // 4 columns per block
    int j  = threadIdx.x;                 // 512 threads
    int c  = j & 3;
    int tb = j >> 2;                      // [0, 128)

    const float2* spec = d_spec + (b << 20) + c0 + c;
    // stage 0: gmem -> shared, exploiting the zero middle band
#pragma unroll
    for (int q = 0; q < 4; q++) {
        int u = tb + (q << 7);            // butterfly index in [0, 512)
        float2 wp = d_tw[u];
        float2 v, s0, s1;
        if (u < 256) {
            v = spec[(size_t)u << 10];            // x[u] nonzero, x[u+512] zero
            s0 = v;
            s1 = cmulf(v, wp);
        } else {
            v = spec[(size_t)(u + 512) << 10];    // x[u] zero, x[u+512] nonzero
            s0 = v;
            s1 = cmulf(make_float2(-v.x, -v.y), wp);
        }
        x[((2 * u) << 2) + c]     = s0;
        x[((2 * u + 1) << 2) + c] = s1;
    }
    __syncthreads();

#pragma unroll
    for (int k = 1; k < 10; k++) {
        int s = 1 << k;
#pragma unroll
        for (int q = 0; q < 4; q++) {
            int u  = tb + (q << 7);
            int sp = u & ~(s - 1);
            float2 a  = x[(u << 2) + c];
            float2 cc = x[((u + 512) << 2) + c];
            float2 wp = d_tw[sp];
            float2 sum = make_float2(a.x + cc.x, a.y + cc.y);
            float2 dif = make_float2(a.x - cc.x, a.y - cc.y);
            y[((u + sp) << 2) + c]     = sum;
            y[((u + sp + s) << 2) + c] = cmulf(dif, wp);
        }
        __syncthreads();
        float2* tmp = x; x = y; y = tmp;
    }

    // epilogue: write padded gather buffers (body columns only)
    int t = threadIdx.x;
    int jm1 = (c0 + 1023) & 1023;         // gO column fed by our c==0 value
    float2* gE2 = (float2*)d_gE + (size_t)b * (NG * ROWC);
    float2* gO2 = (float2*)d_gO + (size_t)b * (NG * ROWC);
#pragma unroll
    for (int h = 0; h < 2; h++) {
        int r = t + h * 512;
        float2 v0 = x[(r << 2) + 0];
        float2 v1 = x[(r << 2) + 1];
        float2 v2 = x[(r << 2) + 2];
        float2 v3 = x[(r << 2) + 3];
        size_t rowb = (size_t)r * ROWC;
        // gE[r][c0..c0+3] as two float4 stores (c0 multiple of 4 -> aligned)
        float4* ge4 = (float4*)(gE2 + rowb + c0);
        ge4[0] = make_float4(v0.x, v0.y, v1.x, v1.y);
        ge4[1] = make_float4(v2.x, v2.y, v3.x, v3.y);
        // gO[r][jm1] = g[r][c0]; gO[r][c0+i] = g[r][c0+i+1] for i=0..2
        gO2[rowb + jm1]    = v0;
        gO2[rowb + c0]     = v1;
        gO2[rowb + c0 + 1] = v2;
        gO2[rowb + c0 + 2] = v3;
    }
}

// ---------------- tiny wrap-column fixup: cols 1024..1031 copy cols 0..7 ----------------
__global__ void pad_fix_kernel() {
    int gid = blockIdx.x * blockDim.x + threadIdx.x;   // [0, 2*1024*8*2)
    int i   = gid & 7;
    int r   = (gid >> 3) & 1023;
    int bb  = gid >> 13;                  // b*2 + which buffer
    int b   = bb >> 1;
    float2* g2 = (float2*)((bb & 1) ? d_gO : d_gE) + (size_t)b * (NG * ROWC)
               + (size_t)r * ROWC;
    g2[1024 + i] = g2[i];
}

// ---------------- Kaiser-Bessel time-domain window ----------------
__device__ __forceinline__ float kbwin(float s) {
    float u2 = fmaf(-s, s, 16.0f);            // M^2 - s^2
    if (u2 <= 0.0f) return 0.0f;
    float rinv = rsqrtf(u2);                  // 1/u
    float u    = u2 * rinv;
    float e    = __expf(BETA_F * u);
    float einv = __fdividef(1.0f, e);
    return (e - einv) * rinv * 0.159154943091895336f;  // sinh(b u)/(pi u)
}

// ---------------- per-point 8x8 gather ----------------
__global__ void __launch_bounds__(256) gather_kernel(const float* __restrict__ xin,
                                                     float* __restrict__ out) {
    int gid = blockIdx.x * blockDim.x + threadIdx.x;   // [0, NB*NP)
    int b = gid >> 19;
    float2 xy = ((const float2*)xin)[gid];

    float xn1 = xy.x * 1024.0f;
    float fl1 = floorf(xn1);
    int   l01 = (int)fl1;
    float fr1 = xn1 - fl1;

    float xn2 = xy.y * 1024.0f;
    float fl2 = floorf(xn2);
    int   l02 = (int)fl2;
    float fr2 = xn2 - fl2;

    float w1[8], w2[8];
#pragma unroll
    for (int t = 0; t < 8; t++) {
        float o = (float)(t - 3);
        w1[t] = kbwin(fr1 - o);
        w2[t] = kbwin(fr2 - o);
    }

    int c0 = (l02 - 3) & 1023;
    const float4* gbase = ((c0 & 1) ? d_gO : d_gE)
                        + (size_t)b * (NG * ROWF4) + (c0 >> 1);

    float accre = 0.0f, accim = 0.0f;
#pragma unroll
    for (int i = 0; i < 8; i++) {
        int r = (l01 + i - 3) & 1023;
        const float4* rp = gbase + r * ROWF4;
        float4 q0 = __ldg(rp + 0);
        float4 q1 = __ldg(rp + 1);
        float4 q2 = __ldg(rp + 2);
        float4 q3 = __ldg(rp + 3);
        float sre = w2[0]*q0.x + w2[1]*q0.z + w2[2]*q1.x + w2[3]*q1.z
                  + w2[4]*q2.x + w2[5]*q2.z + w2[6]*q3.x + w2[7]*q3.z;
        float sim = w2[0]*q0.y + w2[1]*q0.w + w2[2]*q1.y + w2[3]*q1.w
                  + w2[4]*q2.y + w2[5]*q2.w + w2[6]*q3.y + w2[7]*q3.w;
        accre = fmaf(w1[i], sre, accre);
        accim = fmaf(w1[i], sim, accim);
    }
    ((float2*)out)[gid] = make_float2(accre, accim);
}

// ---------------- launch ----------------
extern "C" void kernel_launch(void* const* d_in, const int* in_sizes, int n_in,
                              void* d_out, int out_size) {
    const float* xin = (const float*)d_in[0];   // [B, P, 2]
    const float* fh  = (const float*)d_in[1];   // [B,512,512,2]
    if (n_in >= 2 && in_sizes[0] < in_sizes[1]) {
        const float* t = xin; xin = fh; fh = t;
    }
    cudaFuncSetAttribute(fft_cols_fused,
                         cudaFuncAttributeMaxDynamicSharedMemorySize, 65536);
    init_kernel<<<4, 256>>>();
    fft_rows_fused<<<NB * 512, 512>>>(fh);
    fft_cols_fused<<<NB * 256, 512, 65536>>>();
    pad_fix_kernel<<<(NB * NG * 8 * 2) / 256, 256>>>();
    gather_kernel<<<(NB * NP) / 256, 256>>>(xin, (float*)d_out);
}

// round 4
// speedup vs baseline: 1.4305x; 1.2956x over previous
#include <cuda_runtime.h>

#define NB 2
#define NP 524288           // points per batch
#define NG 1024             // oversampled grid per dim
#define NF 512              // frequency grid per dim
#define ROWC 1032           // padded row length in complex (8 wrap columns)
#define ROWF4 516           // padded row length in float4 (2 complex each)
#define BETA_F 4.712388980384690f   // 1.5*pi
#define DPI 3.14159265358979323846

// ---------------- static device scratch (no allocations allowed) ----------------
__device__ float2 d_spec[NB * NG * NG];        // row-FFT result (only 512 rows/batch valid)
__device__ float4 d_gE[NB * NG * ROWF4];       // even-parity padded copy of g
__device__ float4 d_gO[NB * NG * ROWF4];       // shifted-by-one padded copy of g
__device__ float  d_cinv[NF];                  // 1 / I0(M*arg) deconvolution coefficients
__device__ float2 d_tw[NG];                    // e^{-2 pi i j / 1024}

// ---------------- init: deconvolution coefficients + twiddles ----------------
__global__ void init_kernel() {
    int t = blockIdx.x * blockDim.x + threadIdx.x;
    if (t < NF) {
        double k   = (double)(t - 256);
        double w   = 2.0 * DPI * k / 1024.0;
        double bet = 1.5 * DPI;
        double arg = sqrt(bet * bet - w * w);
        double x   = 4.0 * arg;                 // M * arg, always >= 17.7
        double tt = 3.75 / x;
        double poly = 0.39894228 + tt*(0.01328592 + tt*(0.00225319 + tt*(-0.00157565 +
                      tt*(0.00916281 + tt*(-0.02057706 + tt*(0.02635537 +
                      tt*(-0.01647633 + tt*0.00392377)))))));
        double i0 = exp(x) / sqrt(x) * poly;
        d_cinv[t] = (float)(1.0 / i0);          // (1024/i0)^2 * (1/1024^2) == (1/i0)^2
    }
    if (t < NG) {
        double th = -2.0 * DPI * (double)t / 1024.0;
        d_tw[t] = make_float2((float)cos(th), (float)sin(th));
    }
}

__device__ __forceinline__ float2 cmulf(float2 a, float2 b) {
    return make_float2(a.x * b.x - a.y * b.y, a.x * b.y + a.y * b.x);
}

// ---------------- fused: deconvolve + ifftshift + 1024-pt row FFT ----------------
__global__ void fft_rows_fused(const float* __restrict__ fhat) {
    __shared__ float2 sA[1024];
    __shared__ float2 sB[1024];
    int bi = blockIdx.x;                  // [0, 1024): 2 batches x 512 nonzero rows
    int b  = bi >> 9;
    int rr = bi & 511;
    int m1 = (rr < 256) ? rr : rr + 512;        // output spectrum row
    int i1 = (rr < 256) ? rr + 256 : rr - 256;  // source fhat row
    float ci1 = d_cinv[i1];
    const float2* fh = (const float2*)fhat + (size_t)(b * 512 + i1) * 512;
    int t = threadIdx.x;                  // 512 threads
#pragma unroll
    for (int h = 0; h < 2; h++) {
        int m2 = t + h * 512;
        float2 v = make_float2(0.0f, 0.0f);
        if (m2 < 256 || m2 >= 768) {
            int i2 = (m2 < 256) ? m2 + 256 : m2 - 768;
            float2 f = fh[i2];
            float s = ci1 * d_cinv[i2];
            v = make_float2(f.x * s, f.y * s);
        }
        sA[m2] = v;
    }
    __syncthreads();
    float2* x = sA;
    float2* y = sB;
#pragma unroll
    for (int k = 0; k < 10; k++) {
        int s  = 1 << k;
        int sp = t & ~(s - 1);
        float2 a  = x[t];
        float2 c  = x[t + 512];
        float2 wp = d_tw[sp];
        float2 sum = make_float2(a.x + c.x, a.y + c.y);
        float2 dif = make_float2(a.x - c.x, a.y - c.y);
        y[t + sp]     = sum;
        y[t + sp + s] = cmulf(dif, wp);
        __syncthreads();
        float2* tmp = x; x = y; y = tmp;
    }
    float2* base = d_spec + (b << 20) + (m1 << 10);
    base[t]       = x[t];
    base[t + 512] = x[t + 512];
}

// ---------------- fused: 4-column 1024-pt FFT + gE/gO epilogue (incl. wrap cols) ----------------
__global__ void fft_cols_fused() {
    extern __shared__ float2 sm[];        // [0,4096) = buf A, [4096,8192) = buf B
    float2* x = sm;
    float2* y = sm + 4096;
    int bi = blockIdx.x;                  // [0, 512)
    int b  = bi >> 8;
    int c0 = (bi & 255) << 2;             // 4 columns per block
    int j  = threadIdx.x;                 // 512 threads
    int c  = j & 3;
    int tb = j >> 2;                      // [0, 128)

    const float2* spec = d_spec + (b << 20) + c0 + c;
    // stage 0: gmem -> shared, exploiting the zero middle band
#pragma unroll
    for (int q = 0; q < 4; q++) {
        int u = tb + (q << 7);            // butterfly index in [0, 512)
        float2 wp = d_tw[u];
        float2 v, s0, s1;
        if (u < 256) {
            v = spec[(size_t)u << 10];            // x[u] nonzero, x[u+512] zero
            s0 = v;
            s1 = cmulf(v, wp);
        } else {
            v = spec[(size_t)(u + 512) << 10];    // x[u] zero, x[u+512] nonzero
            s0 = v;
            s1 = cmulf(make_float2(-v.x, -v.y), wp);
        }
        x[((2 * u) << 2) + c]     = s0;
        x[((2 * u + 1) << 2) + c] = s1;
    }
    __syncthreads();

#pragma unroll
    for (int k = 1; k < 10; k++) {
        int s = 1 << k;
#pragma unroll
        for (int q = 0; q < 4; q++) {
            int u  = tb + (q << 7);
            int sp = u & ~(s - 1);
            float2 a  = x[(u << 2) + c];
            float2 cc = x[((u + 512) << 2) + c];
            float2 wp = d_tw[sp];
            float2 sum = make_float2(a.x + cc.x, a.y + cc.y);
            float2 dif = make_float2(a.x - cc.x, a.y - cc.y);
            y[((u + sp) << 2) + c]     = sum;
            y[((u + sp + s) << 2) + c] = cmulf(dif, wp);
        }
        __syncthreads();
        float2* tmp = x; x = y; y = tmp;
    }

    // epilogue: write padded gather buffers, duplicating wrap columns (<8) at +1024
    int t = threadIdx.x;
    int jm1 = (c0 + 1023) & 1023;         // gO column fed by our c==0 value
    float2* gE2 = (float2*)d_gE + (size_t)b * (NG * ROWC);
    float2* gO2 = (float2*)d_gO + (size_t)b * (NG * ROWC);
#pragma unroll
    for (int h = 0; h < 2; h++) {
        int r = t + h * 512;
        float2 v0 = x[(r << 2) + 0];
        float2 v1 = x[(r << 2) + 1];
        float2 v2 = x[(r << 2) + 2];
        float2 v3 = x[(r << 2) + 3];
        size_t rowb = (size_t)r * ROWC;
        float4* ge4 = (float4*)(gE2 + rowb + c0);
        ge4[0] = make_float4(v0.x, v0.y, v1.x, v1.y);
        ge4[1] = make_float4(v2.x, v2.y, v3.x, v3.y);
        if (c0 < 8) {                      // wrap duplicate for gE cols 0..7
            float4* ge4w = (float4*)(gE2 + rowb + 1024 + c0);
            ge4w[0] = ge4[0];
            ge4w[1] = ge4[1];
        }
        gO2[rowb + jm1]    = v0;
        gO2[rowb + c0]     = v1;
        gO2[rowb + c0 + 1] = v2;
        gO2[rowb + c0 + 2] = v3;
        // wrap duplicates for gO cols 0..7 (cols written here: jm1, c0, c0+1, c0+2)
        if (jm1 < 8)      gO2[rowb + 1024 + jm1]    = v0;
        if (c0 < 8) {
            gO2[rowb + 1024 + c0]     = v1;
            if (c0 + 1 < 8) gO2[rowb + 1024 + c0 + 1] = v2;
            if (c0 + 2 < 8) gO2[rowb + 1024 + c0 + 2] = v3;
        }
    }
}

// ---------------- Kaiser-Bessel time-domain window ----------------
__device__ __forceinline__ float kbwin(float s) {
    float u2 = fmaf(-s, s, 16.0f);            // M^2 - s^2
    if (u2 <= 0.0f) return 0.0f;
    float rinv = rsqrtf(u2);                  // 1/u
    float u    = u2 * rinv;
    float e    = __expf(BETA_F * u);
    float einv = __fdividef(1.0f, e);
    return (e - einv) * rinv * 0.159154943091895336f;  // sinh(b u)/(pi u)
}

// ---------------- per-point 8x8 gather: 4 lanes cooperate per point ----------------
__global__ void __launch_bounds__(256) gather_kernel(const float* __restrict__ xin,
                                                     float* __restrict__ out) {
    int tid  = blockIdx.x * blockDim.x + threadIdx.x;
    int c    = tid & 3;                   // lane's float4 column within the patch row
    int p    = tid >> 2;                  // point id, [0, NB*NP)
    int b    = p >> 19;
    float2 xy = ((const float2*)xin)[p];

    float xn1 = xy.x * 1024.0f;
    float fl1 = floorf(xn1);
    int   l01 = (int)fl1;
    float fr1 = xn1 - fl1;

    float xn2 = xy.y * 1024.0f;
    float fl2 = floorf(xn2);
    int   l02 = (int)fl2;
    float fr2 = xn2 - fl2;

    // row weights (shared across the 4 lanes, computed redundantly - cheap)
    float w1[8];
#pragma unroll
    for (int t = 0; t < 8; t++)
        w1[t] = kbwin(fr1 - (float)(t - 3));
    // this lane's two column weights (taps 2c, 2c+1)
    float w2a = kbwin(fr2 - (float)(2 * c - 3));
    float w2b = kbwin(fr2 - (float)(2 * c - 2));

    int c0 = (l02 - 3) & 1023;
    const float4* gbase = ((c0 & 1) ? d_gO : d_gE)
                        + (size_t)b * (NG * ROWF4) + (c0 >> 1) + c;

    float accre = 0.0f, accim = 0.0f;
#pragma unroll
    for (int i = 0; i < 8; i++) {
        int r = (l01 + i - 3) & 1023;
        float4 q = __ldg(gbase + r * ROWF4);
        float sre = w2a * q.x + w2b * q.z;
        float sim = w2a * q.y + w2b * q.w;
        accre = fmaf(w1[i], sre, accre);
        accim = fmaf(w1[i], sim, accim);
    }
    // reduce across the 4 cooperating lanes
    accre += __shfl_xor_sync(0xffffffffu, accre, 1);
    accim += __shfl_xor_sync(0xffffffffu, accim, 1);
    accre += __shfl_xor_sync(0xffffffffu, accre, 2);
    accim += __shfl_xor_sync(0xffffffffu, accim, 2);
    if (c == 0)
        ((float2*)out)[p] = make_float2(accre, accim);
}

// ---------------- launch ----------------
extern "C" void kernel_launch(void* const* d_in, const int* in_sizes, int n_in,
                              void* d_out, int out_size) {
    const float* xin = (const float*)d_in[0];   // [B, P, 2]
    const float* fh  = (const float*)d_in[1];   // [B,512,512,2]
    if (n_in >= 2 && in_sizes[0] < in_sizes[1]) {
        const float* t = xin; xin = fh; fh = t;
    }
    cudaFuncSetAttribute(fft_cols_fused,
                         cudaFuncAttributeMaxDynamicSharedMemorySize, 65536);
    init_kernel<<<4, 256>>>();
    fft_rows_fused<<<NB * 512, 512>>>(fh);
    fft_cols_fused<<<NB * 256, 512, 65536>>>();
    gather_kernel<<<(NB * NP * 4) / 256, 256>>>(xin, (float*)d_out);
}

// round 6
// speedup vs baseline: 1.4966x; 1.0462x over previous
#include <cuda_runtime.h>

#define NB 2
#define NP 524288           // points per batch
#define NG 1024             // oversampled grid per dim
#define NF 512              // frequency grid per dim
#define ROWC 1032           // padded row length in complex (8 wrap columns)
#define ROWF4 516           // padded row length in float4 (2 complex each)
#define NROWA 1032          // allocated rows (1024 + 7 wrap rows, padded to 1032)
#define BETA_F 4.712388980384690f   // 1.5*pi
#define DPI 3.14159265358979323846

// ---------------- static device scratch (no allocations allowed) ----------------
__device__ float2 d_spec[NB * NG * NG];        // row-FFT result (only 512 rows/batch valid)
__device__ float4 d_gE[NB * NROWA * ROWF4];    // even-parity padded copy of g (rows+cols wrapped)
__device__ float4 d_gO[NB * NROWA * ROWF4];    // shifted-by-one padded copy of g
__device__ float  d_cinv[NF];                  // 1 / I0(M*arg) deconvolution coefficients
__device__ float2 d_tw[NG];                    // e^{-2 pi i j / 1024}

// ---------------- init: deconvolution coefficients + twiddles ----------------
__global__ void init_kernel() {
    int t = blockIdx.x * blockDim.x + threadIdx.x;
    if (t < NF) {
        double k   = (double)(t - 256);
        double w   = 2.0 * DPI * k / 1024.0;
        double bet = 1.5 * DPI;
        double arg = sqrt(bet * bet - w * w);
        double x   = 4.0 * arg;                 // M * arg, always >= 17.7
        double tt = 3.75 / x;
        double poly = 0.39894228 + tt*(0.01328592 + tt*(0.00225319 + tt*(-0.00157565 +
                      tt*(0.00916281 + tt*(-0.02057706 + tt*(0.02635537 +
                      tt*(-0.01647633 + tt*0.00392377)))))));
        double i0 = exp(x) / sqrt(x) * poly;
        d_cinv[t] = (float)(1.0 / i0);          // (1024/i0)^2 * (1/1024^2) == (1/i0)^2
    }
    if (t < NG) {
        double th = -2.0 * DPI * (double)t / 1024.0;
        d_tw[t] = make_float2((float)cos(th), (float)sin(th));
    }
}

__device__ __forceinline__ float2 cmulf(float2 a, float2 b) {
    return make_float2(a.x * b.x - a.y * b.y, a.x * b.y + a.y * b.x);
}

// ---------------- fused: deconvolve + ifftshift + 1024-pt row FFT ----------------
__global__ void fft_rows_fused(const float* __restrict__ fhat) {
    __shared__ float2 sA[1024];
    __shared__ float2 sB[1024];
    int bi = blockIdx.x;                  // [0, 1024): 2 batches x 512 nonzero rows
    int b  = bi >> 9;
    int rr = bi & 511;
    int m1 = (rr < 256) ? rr : rr + 512;        // output spectrum row
    int i1 = (rr < 256) ? rr + 256 : rr - 256;  // source fhat row
    float ci1 = d_cinv[i1];
    const float2* fh = (const float2*)fhat + (size_t)(b * 512 + i1) * 512;
    int t = threadIdx.x;                  // 512 threads
#pragma unroll
    for (int h = 0; h < 2; h++) {
        int m2 = t + h * 512;
        float2 v = make_float2(0.0f, 0.0f);
        if (m2 < 256 || m2 >= 768) {
            int i2 = (m2 < 256) ? m2 + 256 : m2 - 768;
            float2 f = fh[i2];
            float s = ci1 * d_cinv[i2];
            v = make_float2(f.x * s, f.y * s);
        }
        sA[m2] = v;
    }
    __syncthreads();
    float2* x = sA;
    float2* y = sB;
#pragma unroll
    for (int k = 0; k < 10; k++) {
        int s  = 1 << k;
        int sp = t & ~(s - 1);
        float2 a  = x[t];
        float2 c  = x[t + 512];
        float2 wp = d_tw[sp];
        float2 sum = make_float2(a.x + c.x, a.y + c.y);
        float2 dif = make_float2(a.x - c.x, a.y - c.y);
        y[t + sp]     = sum;
        y[t + sp + s] = cmulf(dif, wp);
        __syncthreads();
        float2* tmp = x; x = y; y = tmp;
    }
    float2* base = d_spec + (b << 20) + (m1 << 10);
    base[t]       = x[t];
    base[t + 512] = x[t + 512];
}

// ---------------- fused: 4-column 1024-pt FFT + gE/gO epilogue ----------------
// Epilogue writes the padded gather buffers with BOTH column wrap (cols 1024..1031
// duplicate 0..7) and row wrap (rows 1024..1030 duplicate 0..6).
__global__ void fft_cols_fused() {
    extern __shared__ float2 sm[];        // [0,4096) = buf A, [4096,8192) = buf B
    float2* x = sm;
    float2* y = sm + 4096;
    int bi = blockIdx.x;                  // [0, 512)
    int b  = bi >> 8;
    int c0 = (bi & 255) << 2;             // 4 columns per block
    int j  = threadIdx.x;                 // 512 threads
    int c  = j & 3;
    int tb = j >> 2;                      // [0, 128)

    const float2* spec = d_spec + (b << 20) + c0 + c;
    // stage 0: gmem -> shared, exploiting the zero middle band
#pragma unroll
    for (int q = 0; q < 4; q++) {
        int u = tb + (q << 7);            // butterfly index in [0, 512)
        float2 wp = d_tw[u];
        float2 v, s0, s1;
        if (u < 256) {
            v = spec[(size_t)u << 10];            // x[u] nonzero, x[u+512] zero
            s0 = v;
            s1 = cmulf(v, wp);
        } else {
            v = spec[(size_t)(u + 512) << 10];    // x[u] zero, x[u+512] nonzero
            s0 = v;
            s1 = cmulf(make_float2(-v.x, -v.y), wp);
        }
        x[((2 * u) << 2) + c]     = s0;
        x[((2 * u + 1) << 2) + c] = s1;
    }
    __syncthreads();

#pragma unroll
    for (int k = 1; k < 10; k++) {
        int s = 1 << k;
#pragma unroll
        for (int q = 0; q < 4; q++) {
            int u  = tb + (q << 7);
            int sp = u & ~(s - 1);
            float2 a  = x[(u << 2) + c];
            float2 cc = x[((u + 512) << 2) + c];
            float2 wp = d_tw[sp];
            float2 sum = make_float2(a.x + cc.x, a.y + cc.y);
            float2 dif = make_float2(a.x - cc.x, a.y - cc.y);
            y[((u + sp) << 2) + c]     = sum;
            y[((u + sp + s) << 2) + c] = cmulf(dif, wp);
        }
        __syncthreads();
        float2* tmp = x; x = y; y = tmp;
    }

    // epilogue
    int t = threadIdx.x;
    int jm1 = (c0 + 1023) & 1023;         // gO column fed by our c==0 value
    float2* gE2 = (float2*)d_gE + (size_t)b * (NROWA * ROWC);
    float2* gO2 = (float2*)d_gO + (size_t)b * (NROWA * ROWC);
#pragma unroll
    for (int h = 0; h < 2; h++) {
        int r = t + h * 512;
        float2 v0 = x[(r << 2) + 0];
        float2 v1 = x[(r << 2) + 1];
        float2 v2 = x[(r << 2) + 2];
        float2 v3 = x[(r << 2) + 3];
#pragma unroll
        for (int rep = 0; rep < 2; rep++) {
            if (rep == 1 && r >= 7) break;          // row wrap: rows 0..6 -> 1024..1030
            size_t rowb = (size_t)(r + rep * 1024) * ROWC;
            float4* ge4 = (float4*)(gE2 + rowb + c0);
            float4 a0 = make_float4(v0.x, v0.y, v1.x, v1.y);
            float4 a1 = make_float4(v2.x, v2.y, v3.x, v3.y);
            ge4[0] = a0;
            ge4[1] = a1;
            if (c0 < 8) {                 // column wrap for gE cols 0..7
                float4* ge4w = (float4*)(gE2 + rowb + 1024 + c0);
                ge4w[0] = a0;
                ge4w[1] = a1;
            }
            gO2[rowb + jm1]    = v0;
            gO2[rowb + c0]     = v1;
            gO2[rowb + c0 + 1] = v2;
            gO2[rowb + c0 + 2] = v3;
            if (jm1 < 8)      gO2[rowb + 1024 + jm1]    = v0;
            if (c0 < 8) {
                gO2[rowb + 1024 + c0]     = v1;
                if (c0 + 1 < 8) gO2[rowb + 1024 + c0 + 1] = v2;
                if (c0 + 2 < 8) gO2[rowb + 1024 + c0 + 2] = v3;
            }
        }
    }
}

// ---------------- Kaiser-Bessel time-domain window (one-sided exp approx) ----------------
// sinh(b u)/(pi u) = (e^{bu} - e^{-bu}) / (2 pi u); the e^{-bu} term is dropped.
// Worst-case absolute tap error ~O(100) vs a central weight of ~6e6 -> <3e-5 relative.
__device__ __forceinline__ float kbwin(float s) {
    float u2 = fmaf(-s, s, 16.0f);            // M^2 - s^2
    if (u2 <= 0.0f) return 0.0f;
    float rinv = rsqrtf(u2);                  // 1/u
    float u    = u2 * rinv;
    return __expf(BETA_F * u) * rinv * 0.159154943091895336f;  // e^{bu}/(2 pi u)
}

// ---------------- per-point 8x8 gather: 4 lanes cooperate per point ----------------
__global__ void __launch_bounds__(256) gather_kernel(const float* __restrict__ xin,
                                                     float* __restrict__ out) {
    int tid  = blockIdx.x * blockDim.x + threadIdx.x;
    int c    = tid & 3;                   // lane's float4 column within the patch row
    int p    = tid >> 2;                  // point id, [0, NB*NP)
    int b    = p >> 19;
    float2 xy = ((const float2*)xin)[p];

    float xn1 = xy.x * 1024.0f;
    float fl1 = floorf(xn1);
    int   l01 = (int)fl1;
    float fr1 = xn1 - fl1;

    float xn2 = xy.y * 1024.0f;
    float fl2 = floorf(xn2);
    int   l02 = (int)fl2;
    float fr2 = xn2 - fl2;

    // lane c owns taps 2c and 2c+1 of each dimension (4 kbwin total per lane)
    float o0  = (float)(2 * c - 3);
    float w1a = kbwin(fr1 - o0);
    float w1b = kbwin(fr1 - o0 - 1.0f);
    float w2a = kbwin(fr2 - o0);
    float w2b = kbwin(fr2 - o0 - 1.0f);

    // broadcast the 8 row weights across the 4-lane group
    float w1[8];
#pragma unroll
    for (int d = 0; d < 4; d++) {
        w1[2 * d]     = __shfl_sync(0xffffffffu, w1a, d, 4);
        w1[2 * d + 1] = __shfl_sync(0xffffffffu, w1b, d, 4);
    }

    int r0 = (l01 - 3) & 1023;
    int c0 = (l02 - 3) & 1023;
    const float4* gp = ((c0 & 1) ? d_gO : d_gE)
                     + (size_t)b * (NROWA * ROWF4) + (size_t)r0 * ROWF4 + (c0 >> 1) + c;

    float accre = 0.0f, accim = 0.0f;
#pragma unroll
    for (int i = 0; i < 8; i++) {
        float4 q = __ldg(gp + i * ROWF4);   // constant offsets: no per-iter index math
        float sre = w2a * q.x + w2b * q.z;
        float sim = w2a * q.y + w2b * q.w;
        accre = fmaf(w1[i], sre, accre);
        accim = fmaf(w1[i], sim, accim);
    }
    // reduce across the 4 cooperating lanes
    accre += __shfl_xor_sync(0xffffffffu, accre, 1);
    accim += __shfl_xor_sync(0xffffffffu, accim, 1);
    accre += __shfl_xor_sync(0xffffffffu, accre, 2);
    accim += __shfl_xor_sync(0xffffffffu, accim, 2);
    if (c == 0)
        ((float2*)out)[p] = make_float2(accre, accim);
}

// ---------------- launch ----------------
extern "C" void kernel_launch(void* const* d_in, const int* in_sizes, int n_in,
                              void* d_out, int out_size) {
    const float* xin = (const float*)d_in[0];   // [B, P, 2]
    const float* fh  = (const float*)d_in[1];   // [B,512,512,2]
    if (n_in >= 2 && in_sizes[0] < in_sizes[1]) {
        const float* t = xin; xin = fh; fh = t;
    }
    cudaFuncSetAttribute(fft_cols_fused,
                         cudaFuncAttributeMaxDynamicSharedMemorySize, 65536);
    init_kernel<<<4, 256>>>();
    fft_rows_fused<<<NB * 512, 512>>>(fh);
    fft_cols_fused<<<NB * 256, 512, 65536>>>();
    gather_kernel<<<(NB * NP * 4) / 256, 256>>>(xin, (float*)d_out);
}